// round 5
// baseline (speedup 1.0000x reference)
#include <cuda_runtime.h>
#include <cstddef>

// ---------------------------------------------------------------------------
//   stage12: per image: conv1(3->3,k3,s2)+maxpool3+relu  (smem-resident)
//            -> conv2(3->1,k3,s2)+maxpool3+relu -> 36->6 linear -> g_nf
//   stage3 : message passing + MLP head -> out[64,6]
// ---------------------------------------------------------------------------

#define IMGS 1280

__device__ float g_nf[IMGS * 6];

// Dynamic smem layout (floats):
//   st   : 3ch x 19rows x 224           = 12768   (input staging, ch stride 4256)
//   outb : 3ch x 37 x 37                =  4107   (pooled conv1 output)
//   w1s  : [ci][oc][kh][kw]             =    81
//   w2s  : [ci][kh][kw]                 =    27
//   lws  : [6][36]                      =   216
//   lbs  : [6]                          =     6
//   bs   : conv1 bias (3) + conv2 bias  =     4
//   s2   : 36
#define ST_OFF    0
#define OUT_OFF   12768
#define W1_OFF    (OUT_OFF + 4107)
#define W2_OFF    (W1_OFF + 81)
#define LW_OFF    (W2_OFF + 27)
#define LB_OFF    (LW_OFF + 216)
#define BS_OFF    (LB_OFF + 6)
#define S2_OFF    (BS_OFF + 4)
#define SMEM_FLOATS (S2_OFF + 36)
#define SMEM_BYTES  (SMEM_FLOATS * 4)

__global__ __launch_bounds__(128) void stage12_kernel(
    const float* __restrict__ nodes,
    const float* __restrict__ w1g,   // [oc][ci][3][3]
    const float* __restrict__ b1g,   // [3]
    const float* __restrict__ w2g,   // [1][3][3][3]
    const float* __restrict__ b2g,   // [1]
    const float* __restrict__ linw,  // [6][36]
    const float* __restrict__ linb)  // [6]
{
    extern __shared__ float sm[];
    float* st   = sm + ST_OFF;
    float* outb = sm + OUT_OFF;
    float* w1s  = sm + W1_OFF;
    float* w2s  = sm + W2_OFF;
    float* lws  = sm + LW_OFF;
    float* lbs  = sm + LB_OFF;
    float* bs   = sm + BS_OFF;
    float* s2   = sm + S2_OFF;

    const int img = blockIdx.x;
    const int tid = threadIdx.x;

    // ---- one-time parameter staging ----
    if (tid < 81) {
        // reorder [oc][ci][k] -> [ci][oc][k]
        int oc = tid / 27, rem = tid - oc * 27;
        int ci = rem / 9,  k   = rem - ci * 9;
        w1s[ci * 27 + oc * 9 + k] = w1g[tid];
    }
    if (tid < 27)  w2s[tid] = w2g[tid];
    for (int i = tid; i < 216; i += 128) lws[i] = linw[i];   // FIXED: full coverage
    if (tid < 6)   lbs[tid] = linb[tid];
    if (tid < 3)   bs[tid]  = b1g[tid];
    if (tid == 3)  bs[3]    = b2g[0];

    const float* src = nodes + (size_t)img * 150528;

    // ---- 13 groups of (up to) 3 pooled rows ----
    for (int g = 0; g < 13; g++) {
        const int p_base = g * 3;
        const int nrows  = (37 - p_base) < 3 ? (37 - p_base) : 3;  // 3 or 1
        const int cnt    = 6 * nrows + 1;                           // 19 or 7
        const int r0     = 6 * p_base;

        __syncthreads();   // previous group's compute done before restaging
                           // (also covers the one-time parameter staging)

        // coalesced float4 staging: global -> smem
        const int cnt56  = cnt * 56;                // float4s per channel
        const float4* s4 = (const float4*)src;
        float4* d4 = (float4*)st;
        for (int ci = 0; ci < 3; ci++) {
            const float4* sc = s4 + ci * 12544 + r0 * 56;
            float4* dc = d4 + ci * 1064;
            for (int i = tid; i < cnt56; i += 128)
                dc[i] = sc[i];
        }
        __syncthreads();

        const int cells = nrows * 37;
        if (tid < cells) {
            const int pl = tid / 37;
            const int q  = tid - pl * 37;

            float acc[3][3][3];   // [oc][pr][pc]
#pragma unroll
            for (int oc = 0; oc < 3; oc++)
#pragma unroll
                for (int pr = 0; pr < 3; pr++)
#pragma unroll
                    for (int pc = 0; pc < 3; pc++) acc[oc][pr][pc] = 0.f;

#pragma unroll
            for (int ci = 0; ci < 3; ci++) {
                float wl[27];
#pragma unroll
                for (int j = 0; j < 27; j++) wl[j] = w1s[ci * 27 + j];

                const float* base = &st[ci * 4256 + 6 * pl * 224 + 6 * q];
#pragma unroll
                for (int r = 0; r < 7; r++) {
                    // 8B-aligned float2 loads: 8 floats covering cols 6q..6q+7
                    const float2* rp = (const float2*)(base + r * 224);
                    float2 a0 = rp[0], a1 = rp[1], a2 = rp[2], a3 = rp[3];
                    float v[7] = {a0.x, a0.y, a1.x, a1.y, a2.x, a2.y, a3.x};
#pragma unroll
                    for (int pr = 0; pr < 3; pr++) {
                        const int kh = r - 2 * pr;
                        if (kh >= 0 && kh < 3) {
#pragma unroll
                            for (int oc = 0; oc < 3; oc++)
#pragma unroll
                                for (int pc = 0; pc < 3; pc++)
#pragma unroll
                                    for (int kw = 0; kw < 3; kw++)
                                        acc[oc][pr][pc] =
                                            fmaf(v[2 * pc + kw],
                                                 wl[oc * 9 + kh * 3 + kw],
                                                 acc[oc][pr][pc]);
                        }
                    }
                }
            }

            const int p = p_base + pl;
#pragma unroll
            for (int oc = 0; oc < 3; oc++) {
                float m = acc[oc][0][0];
#pragma unroll
                for (int pr = 0; pr < 3; pr++)
#pragma unroll
                    for (int pc = 0; pc < 3; pc++) m = fmaxf(m, acc[oc][pr][pc]);
                outb[oc * 1369 + p * 37 + q] = fmaxf(m + bs[oc], 0.f);
            }
        }
    }
    __syncthreads();

    // ---- conv2 + maxpool3 + relu (36 pooled cells) ----
    if (tid < 36) {
        const int pr = tid / 6, pc = tid - 6 * pr;
        const float bias = bs[3];
        float w[27];
#pragma unroll
        for (int i = 0; i < 27; i++) w[i] = w2s[i];
        float pool = -1e30f;
#pragma unroll
        for (int r = 0; r < 3; r++) {
#pragma unroll
            for (int c = 0; c < 3; c++) {
                const int R = 3 * pr + r;
                const int C = 3 * pc + c;
                float a = bias;
#pragma unroll
                for (int ci = 0; ci < 3; ci++)
#pragma unroll
                    for (int kh = 0; kh < 3; kh++)
#pragma unroll
                        for (int kw = 0; kw < 3; kw++)
                            a = fmaf(outb[ci * 1369 + (2 * R + kh) * 37 + 2 * C + kw],
                                     w[ci * 9 + kh * 3 + kw], a);
                pool = fmaxf(pool, a);
            }
        }
        s2[tid] = fmaxf(pool, 0.f);
    }
    __syncthreads();

    if (tid < 6) {
        float a = lbs[tid];
#pragma unroll
        for (int k = 0; k < 36; k++) a = fmaf(s2[k], lws[tid * 36 + k], a);
        g_nf[img * 6 + tid] = a;
    }
}

// ---------------------------------------------------------------------------
// Stage 3: message passing + MLP head. One block per node (64 blocks).
// ---------------------------------------------------------------------------
__global__ __launch_bounds__(128) void stage3_kernel(
    const float* __restrict__ pos,     // [64,5,4,6]
    const float* __restrict__ attmap,  // [64,5,4,4]
    const float* __restrict__ framew, const float* __restrict__ frameb,
    const float* __restrict__ lastw,  const float* __restrict__ lastb,
    const float* __restrict__ fc1w,   const float* __restrict__ fc1b,
    const float* __restrict__ fc2w,   const float* __restrict__ fc2b,
    const float* __restrict__ fc3w,   const float* __restrict__ fc3b,
    float* __restrict__ out)
{
    const int n   = blockIdx.x;
    const int tid = threadIdx.x;

    __shared__ float msg[120];
    __shared__ float feat[240];
    __shared__ float h1[120];
    __shared__ float h2[60];

    const float* posn = pos + n * 120;

    if (tid < 120) {
        const int f = tid / 24;
        const int j = (tid / 6) % 4;
        const int d = tid % 6;
        float acc = frameb[d];
#pragma unroll
        for (int e = 0; e < 6; e++)
            acc = fmaf(posn[(f * 4 + j) * 6 + e], framew[d * 6 + e], acc);
        msg[tid] = acc;
        feat[f * 48 + j * 12 + d] = g_nf[(n * 20 + f * 4 + j) * 6 + d];
    }
    __syncthreads();

    if (tid < 120) {
        const int f  = tid / 24;
        const int nn = (tid / 6) % 4;
        const int d  = tid % 6;
        const float* att = attmap + n * 80 + f * 16;
        float acc = 0.f;
#pragma unroll
        for (int j = 0; j < 4; j++)
            acc = fmaf(att[j * 4 + nn], msg[f * 24 + j * 6 + d], acc);
        if (f >= 1) {
            float l = lastb[d];
#pragma unroll
            for (int e = 0; e < 6; e++)
                l = fmaf(posn[((f - 1) * 4 + nn) * 6 + e], lastw[d * 6 + e], l);
            acc += l;
        }
        feat[f * 48 + nn * 12 + 6 + d] = acc;
    }
    __syncthreads();

    if (tid < 120) {
        float acc = fc1b[tid];
        const float* wr = fc1w + tid * 240;
#pragma unroll 8
        for (int k = 0; k < 240; k++) acc = fmaf(feat[k], wr[k], acc);
        h1[tid] = fmaxf(acc, 0.f);
    }
    __syncthreads();

    if (tid < 60) {
        float acc = fc2b[tid];
        const float* wr = fc2w + tid * 120;
#pragma unroll 8
        for (int k = 0; k < 120; k++) acc = fmaf(h1[k], wr[k], acc);
        h2[tid] = fmaxf(acc, 0.f);
    }
    __syncthreads();

    if (tid < 6) {
        float acc = fc3b[tid];
#pragma unroll
        for (int k = 0; k < 60; k++) acc = fmaf(h2[k], fc3w[tid * 60 + k], acc);
        out[n * 6 + tid] = acc;
    }
}

// ---------------------------------------------------------------------------
extern "C" void kernel_launch(void* const* d_in, const int* in_sizes, int n_in,
                              void* d_out, int out_size)
{
    const float* nodes  = (const float*)d_in[0];
    const float* pos    = (const float*)d_in[1];
    const float* attmap = (const float*)d_in[2];
    // d_in[3] = depths (unused)
    const float* conv1w = (const float*)d_in[4];
    const float* conv1b = (const float*)d_in[5];
    const float* conv2w = (const float*)d_in[6];
    const float* conv2b = (const float*)d_in[7];
    const float* linw   = (const float*)d_in[8];
    const float* linb   = (const float*)d_in[9];
    const float* framew = (const float*)d_in[10];
    const float* frameb = (const float*)d_in[11];
    const float* lastw  = (const float*)d_in[12];
    const float* lastb  = (const float*)d_in[13];
    const float* fc1w   = (const float*)d_in[14];
    const float* fc1b   = (const float*)d_in[15];
    const float* fc2w   = (const float*)d_in[16];
    const float* fc2b   = (const float*)d_in[17];
    const float* fc3w   = (const float*)d_in[18];
    const float* fc3b   = (const float*)d_in[19];

    cudaFuncSetAttribute(stage12_kernel,
                         cudaFuncAttributeMaxDynamicSharedMemorySize, SMEM_BYTES);

    stage12_kernel<<<IMGS, 128, SMEM_BYTES>>>(nodes, conv1w, conv1b,
                                              conv2w, conv2b, linw, linb);
    stage3_kernel<<<64, 128>>>(pos, attmap, framew, frameb, lastw, lastb,
                               fc1w, fc1b, fc2w, fc2b, fc3w, fc3b,
                               (float*)d_out);
}

// round 6
// speedup vs baseline: 1.3120x; 1.3120x over previous
#include <cuda_runtime.h>
#include <cstddef>

#define IMGS 1280

__device__ float g_pool1[IMGS * 3 * 37 * 37];   // 21 MB scratch
__device__ float g_nf[IMGS * 6];
__device__ float g_sink;                        // DCE-blocker for L2 warmup

// ---------------------------------------------------------------------------
// Stage 1: fused conv1(3->3,k3,s2) + maxpool3 + relu.
// Grid (1280, 13): block (img, g) computes pooled rows 3g..3g+2 (last: row 36).
// Stages 3ch x 19rows x 224 = 51 KB smem; each of 111 compute threads owns one
// pooled cell: loads each 7-float input row once (4x float2) and fans it into
// 27 register accumulators acc[oc][pr][pc]. Zero redundant conv work.
// ---------------------------------------------------------------------------
#define S1_SMEM_FLOATS (3 * 19 * 224 + 84)   // staging + weights/bias pad
#define S1_SMEM_BYTES  (S1_SMEM_FLOATS * 4)

__global__ __launch_bounds__(128, 4) void stage1_kernel(
    const float* __restrict__ nodes,
    const float* __restrict__ w1g,     // [oc][ci][3][3]
    const float* __restrict__ b1g)     // [3]
{
    extern __shared__ float sm[];
    float* st  = sm;                    // 3 x 19 x 224, ch stride 4256
    float* w1s = sm + 3 * 19 * 224;     // [ci][oc][kh][kw] (81)
    float* bsh = w1s + 81;              // [3]

    const int img    = blockIdx.x;
    const int grp    = blockIdx.y;
    const int p_base = grp * 3;
    const int nrows  = (37 - p_base) < 3 ? (37 - p_base) : 3;  // 3 or 1
    const int cnt    = 6 * nrows + 1;                           // 19 or 7
    const int r0     = 6 * p_base;
    const int tid    = threadIdx.x;

    if (tid < 81) {
        int oc = tid / 27, rem = tid - oc * 27;
        int ci = rem / 9,  k   = rem - ci * 9;
        w1s[ci * 27 + oc * 9 + k] = w1g[tid];
    }
    if (tid < 3) bsh[tid] = b1g[tid];

    // coalesced float4 staging: global -> smem
    const float4* s4 = (const float4*)(nodes + (size_t)img * 150528);
    float4* d4 = (float4*)st;
    const int cnt56 = cnt * 56;
#pragma unroll 1
    for (int ci = 0; ci < 3; ci++) {
        const float4* sc = s4 + ci * 12544 + r0 * 56;
        float4* dc = d4 + ci * 1064;
        for (int i = tid; i < cnt56; i += 128)
            dc[i] = sc[i];
    }
    __syncthreads();

    const int cells = nrows * 37;
    if (tid < cells) {
        const int pl = tid / 37;
        const int q  = tid - pl * 37;

        float acc[3][3][3];   // [oc][pr][pc]
#pragma unroll
        for (int oc = 0; oc < 3; oc++)
#pragma unroll
            for (int pr = 0; pr < 3; pr++)
#pragma unroll
                for (int pc = 0; pc < 3; pc++) acc[oc][pr][pc] = 0.f;

#pragma unroll
        for (int ci = 0; ci < 3; ci++) {
            float wl[27];
#pragma unroll
            for (int j = 0; j < 27; j++) wl[j] = w1s[ci * 27 + j];

            const float* base = &st[ci * 4256 + 6 * pl * 224 + 6 * q];
#pragma unroll
            for (int r = 0; r < 7; r++) {
                const float2* rp = (const float2*)(base + r * 224);
                float2 a0 = rp[0], a1 = rp[1], a2 = rp[2], a3 = rp[3];
                float v[7] = {a0.x, a0.y, a1.x, a1.y, a2.x, a2.y, a3.x};
#pragma unroll
                for (int pr = 0; pr < 3; pr++) {
                    const int kh = r - 2 * pr;
                    if (kh >= 0 && kh < 3) {
#pragma unroll
                        for (int oc = 0; oc < 3; oc++)
#pragma unroll
                            for (int pc = 0; pc < 3; pc++)
#pragma unroll
                                for (int kw = 0; kw < 3; kw++)
                                    acc[oc][pr][pc] =
                                        fmaf(v[2 * pc + kw],
                                             wl[oc * 9 + kh * 3 + kw],
                                             acc[oc][pr][pc]);
                    }
                }
            }
        }

        const int p = p_base + pl;
        const size_t ob = (size_t)img * 4107 + (size_t)p * 37 + q;
#pragma unroll
        for (int oc = 0; oc < 3; oc++) {
            float m = acc[oc][0][0];
#pragma unroll
            for (int pr = 0; pr < 3; pr++)
#pragma unroll
                for (int pc = 0; pc < 3; pc++) m = fmaxf(m, acc[oc][pr][pc]);
            g_pool1[ob + oc * 1369] = fmaxf(m + bsh[oc], 0.f);
        }
    }
}

// ---------------------------------------------------------------------------
// Stage 2: conv2 + maxpool3 + relu + 36->6 linear. One block per image.
// Block 0 additionally streams stage3's big weights to warm L2.
// ---------------------------------------------------------------------------
__global__ __launch_bounds__(128) void stage2_kernel(
    const float* __restrict__ w2g,   // [1][3][3][3]
    const float* __restrict__ b2g,   // [1]
    const float* __restrict__ linw,  // [6][36]
    const float* __restrict__ linb,  // [6]
    const float* __restrict__ fc1w,  // warmed for stage3
    const float* __restrict__ fc2w)
{
    const int img = blockIdx.x;
    const int tid = threadIdx.x;

    __shared__ float s[3 * 1369];
    __shared__ float s2[36];

    const float* src = g_pool1 + (size_t)img * 4107;
    for (int i = tid; i < 4107; i += blockDim.x) s[i] = src[i];

    float w[27];
#pragma unroll
    for (int i = 0; i < 27; i++) w[i] = w2g[i];
    const float bias = b2g[0];

    // L2 warm-up of stage3 weights (block 0 only, runs alongside 1279 others)
    if (img == 0) {
        float acc = 0.f;
        const float4* p1 = (const float4*)fc1w;
        for (int i = tid; i < 7200; i += 128) {
            float4 v = p1[i]; acc += v.x + v.y + v.z + v.w;
        }
        const float4* p2 = (const float4*)fc2w;
        for (int i = tid; i < 1800; i += 128) {
            float4 v = p2[i]; acc += v.x + v.y + v.z + v.w;
        }
        if (acc == -1.2345678e33f) g_sink = acc;   // never true; keeps loads live
    }
    __syncthreads();

    if (tid < 36) {
        const int pr = tid / 6, pc = tid - 6 * pr;
        float pool = -1e30f;
#pragma unroll
        for (int r = 0; r < 3; r++) {
#pragma unroll
            for (int c = 0; c < 3; c++) {
                const int R = 3 * pr + r;
                const int C = 3 * pc + c;
                float a = bias;
#pragma unroll
                for (int ci = 0; ci < 3; ci++)
#pragma unroll
                    for (int kh = 0; kh < 3; kh++)
#pragma unroll
                        for (int kw = 0; kw < 3; kw++)
                            a = fmaf(s[ci * 1369 + (2 * R + kh) * 37 + 2 * C + kw],
                                     w[ci * 9 + kh * 3 + kw], a);
                pool = fmaxf(pool, a);
            }
        }
        s2[tid] = fmaxf(pool, 0.f);
    }
    __syncthreads();

    if (tid < 6) {
        float a = linb[tid];
#pragma unroll
        for (int k = 0; k < 36; k++) a = fmaf(s2[k], linw[tid * 36 + k], a);
        g_nf[img * 6 + tid] = a;
    }
}

// ---------------------------------------------------------------------------
// Stage 3: message passing + MLP head. One block per node, 256 threads.
// Every dot product is split-K across thread pairs (tid, tid+128) with
// float4/float2 weight loads; halves combined through smem.
// ---------------------------------------------------------------------------
__global__ __launch_bounds__(256) void stage3_kernel(
    const float* __restrict__ pos,     // [64,5,4,6]
    const float* __restrict__ attmap,  // [64,5,4,4]
    const float* __restrict__ framew, const float* __restrict__ frameb,
    const float* __restrict__ lastw,  const float* __restrict__ lastb,
    const float* __restrict__ fc1w,   const float* __restrict__ fc1b,
    const float* __restrict__ fc2w,   const float* __restrict__ fc2b,
    const float* __restrict__ fc3w,   const float* __restrict__ fc3b,
    float* __restrict__ out)
{
    const int n   = blockIdx.x;
    const int tid = threadIdx.x;
    const int half = tid >> 7;        // 0 or 1
    const int o    = tid & 127;

    __shared__ float msg[120];
    __shared__ __align__(16) float feat[240];
    __shared__ __align__(16) float h1[120];
    __shared__ __align__(16) float h2[60];
    __shared__ float part1[240];
    __shared__ float part2[120];
    __shared__ float part3[12];

    const float* posn = pos + n * 120;

    if (tid < 120) {
        const int f = tid / 24;
        const int j = (tid / 6) % 4;
        const int d = tid % 6;
        float acc = frameb[d];
#pragma unroll
        for (int e = 0; e < 6; e++)
            acc = fmaf(posn[(f * 4 + j) * 6 + e], framew[d * 6 + e], acc);
        msg[tid] = acc;
        feat[f * 48 + j * 12 + d] = g_nf[(n * 20 + f * 4 + j) * 6 + d];
    }
    __syncthreads();

    if (tid < 120) {
        const int f  = tid / 24;
        const int nn = (tid / 6) % 4;
        const int d  = tid % 6;
        const float* att = attmap + n * 80 + f * 16;
        float acc = 0.f;
#pragma unroll
        for (int j = 0; j < 4; j++)
            acc = fmaf(att[j * 4 + nn], msg[f * 24 + j * 6 + d], acc);
        if (f >= 1) {
            float l = lastb[d];
#pragma unroll
            for (int e = 0; e < 6; e++)
                l = fmaf(posn[((f - 1) * 4 + nn) * 6 + e], lastw[d * 6 + e], l);
            acc += l;
        }
        feat[f * 48 + nn * 12 + 6 + d] = acc;
    }
    __syncthreads();

    // fc1: 120 outputs, K=240 split into two 120-halves (30 float4 each)
    if (o < 120) {
        const float4* wr = (const float4*)(fc1w + o * 240 + half * 120);
        const float4* fe = (const float4*)feat + half * 30;
        float acc = 0.f;
#pragma unroll
        for (int k = 0; k < 30; k++) {
            float4 w4 = wr[k], f4 = fe[k];
            acc = fmaf(f4.x, w4.x, acc);
            acc = fmaf(f4.y, w4.y, acc);
            acc = fmaf(f4.z, w4.z, acc);
            acc = fmaf(f4.w, w4.w, acc);
        }
        part1[half * 120 + o] = acc;
    }
    __syncthreads();
    if (tid < 120) h1[tid] = fmaxf(part1[tid] + part1[120 + tid] + fc1b[tid], 0.f);
    __syncthreads();

    // fc2: 60 outputs, K=120 split into two 60-halves (15 float4 each)
    if (o < 60) {
        const float4* wr = (const float4*)(fc2w + o * 120 + half * 60);
        const float4* hh = (const float4*)h1 + half * 15;
        float acc = 0.f;
#pragma unroll
        for (int k = 0; k < 15; k++) {
            float4 w4 = wr[k], f4 = hh[k];
            acc = fmaf(f4.x, w4.x, acc);
            acc = fmaf(f4.y, w4.y, acc);
            acc = fmaf(f4.z, w4.z, acc);
            acc = fmaf(f4.w, w4.w, acc);
        }
        part2[half * 60 + o] = acc;
    }
    __syncthreads();
    if (tid < 60) h2[tid] = fmaxf(part2[tid] + part2[60 + tid] + fc2b[tid], 0.f);
    __syncthreads();

    // fc3: 6 outputs, K=60 split into two 30-halves (15 float2 each)
    if (o < 6) {
        const float2* wr = (const float2*)(fc3w + o * 60 + half * 30);
        const float2* hh = (const float2*)h2 + half * 15;
        float acc = 0.f;
#pragma unroll
        for (int k = 0; k < 15; k++) {
            float2 w2 = wr[k], f2 = hh[k];
            acc = fmaf(f2.x, w2.x, acc);
            acc = fmaf(f2.y, w2.y, acc);
        }
        part3[half * 6 + o] = acc;
    }
    __syncthreads();
    if (tid < 6) out[n * 6 + tid] = part3[tid] + part3[6 + tid] + fc3b[tid];
}

// ---------------------------------------------------------------------------
extern "C" void kernel_launch(void* const* d_in, const int* in_sizes, int n_in,
                              void* d_out, int out_size)
{
    const float* nodes  = (const float*)d_in[0];
    const float* pos    = (const float*)d_in[1];
    const float* attmap = (const float*)d_in[2];
    // d_in[3] = depths (unused)
    const float* conv1w = (const float*)d_in[4];
    const float* conv1b = (const float*)d_in[5];
    const float* conv2w = (const float*)d_in[6];
    const float* conv2b = (const float*)d_in[7];
    const float* linw   = (const float*)d_in[8];
    const float* linb   = (const float*)d_in[9];
    const float* framew = (const float*)d_in[10];
    const float* frameb = (const float*)d_in[11];
    const float* lastw  = (const float*)d_in[12];
    const float* lastb  = (const float*)d_in[13];
    const float* fc1w   = (const float*)d_in[14];
    const float* fc1b   = (const float*)d_in[15];
    const float* fc2w   = (const float*)d_in[16];
    const float* fc2b   = (const float*)d_in[17];
    const float* fc3w   = (const float*)d_in[18];
    const float* fc3b   = (const float*)d_in[19];

    cudaFuncSetAttribute(stage1_kernel,
                         cudaFuncAttributeMaxDynamicSharedMemorySize, S1_SMEM_BYTES);

    dim3 g1(IMGS, 13);
    stage1_kernel<<<g1, 128, S1_SMEM_BYTES>>>(nodes, conv1w, conv1b);
    stage2_kernel<<<IMGS, 128>>>(conv2w, conv2b, linw, linb, fc1w, fc2w);
    stage3_kernel<<<64, 256>>>(pos, attmap, framew, frameb, lastw, lastb,
                               fc1w, fc1b, fc2w, fc2b, fc3w, fc3b,
                               (float*)d_out);
}

// round 7
// speedup vs baseline: 1.6375x; 1.2481x over previous
#include <cuda_runtime.h>
#include <cstddef>

#define IMGS 1280

__device__ float g_pool1[IMGS * 3 * 37 * 37];   // 21 MB scratch
__device__ float g_nf[IMGS * 6];
__device__ float g_sink;                        // DCE-blocker for L2 warmup

// ---------------------------------------------------------------------------
// Stage 1: conv1(3->3,k3,s2) + maxpool3 + relu, streamed directly from GMEM.
// Grid (1280, 11) x 128 threads; thread = one pooled cell (p,q) of one image.
// Each thread reads its 7x7x3 window as 4x LDG.64 per row (8B-aligned since
// col offset 6q -> 24q bytes). Adjacent cells overlap by 1 column -> sectors
// coalesce within the warp; DRAM traffic ~= 1x input size. No smem staging,
// no phase syncs -> continuous DRAM streaming.
// ---------------------------------------------------------------------------
__global__ __launch_bounds__(128) void stage1_kernel(
    const float* __restrict__ nodes,
    const float* __restrict__ w1g,     // [oc][ci][3][3]
    const float* __restrict__ b1g)     // [3]
{
    __shared__ float w1s[81];          // [ci][oc][kh][kw]
    __shared__ float bsh[3];

    const int tid = threadIdx.x;
    if (tid < 81) {
        int oc = tid / 27, rem = tid - oc * 27;
        int ci = rem / 9,  k   = rem - ci * 9;
        w1s[ci * 27 + oc * 9 + k] = w1g[tid];
    }
    if (tid < 3) bsh[tid] = b1g[tid];
    __syncthreads();

    const int img  = blockIdx.x;
    const int cell = blockIdx.y * 128 + tid;     // 0..1407 (1369 valid)
    if (cell >= 1369) return;
    const int p = cell / 37;
    const int q = cell - p * 37;

    const float* base0 = nodes + (size_t)img * 150528 + (size_t)(6 * p) * 224 + 6 * q;

    float acc[3][3][3];   // [oc][pr][pc]
#pragma unroll
    for (int oc = 0; oc < 3; oc++)
#pragma unroll
        for (int pr = 0; pr < 3; pr++)
#pragma unroll
            for (int pc = 0; pc < 3; pc++) acc[oc][pr][pc] = 0.f;

#pragma unroll
    for (int ci = 0; ci < 3; ci++) {
        float wl[27];
#pragma unroll
        for (int j = 0; j < 27; j++) wl[j] = w1s[ci * 27 + j];

        const float* base = base0 + ci * 50176;
#pragma unroll
        for (int r = 0; r < 7; r++) {
            // 8 floats covering cols 6q..6q+7 (only first 7 used)
            const float2* rp = (const float2*)(base + r * 224);
            float2 a0 = __ldg(rp + 0);
            float2 a1 = __ldg(rp + 1);
            float2 a2 = __ldg(rp + 2);
            float2 a3 = __ldg(rp + 3);
            float v[7] = {a0.x, a0.y, a1.x, a1.y, a2.x, a2.y, a3.x};
#pragma unroll
            for (int pr = 0; pr < 3; pr++) {
                const int kh = r - 2 * pr;
                if (kh >= 0 && kh < 3) {
#pragma unroll
                    for (int oc = 0; oc < 3; oc++)
#pragma unroll
                        for (int pc = 0; pc < 3; pc++)
#pragma unroll
                            for (int kw = 0; kw < 3; kw++)
                                acc[oc][pr][pc] =
                                    fmaf(v[2 * pc + kw],
                                         wl[oc * 9 + kh * 3 + kw],
                                         acc[oc][pr][pc]);
                }
            }
        }
    }

    const size_t ob = (size_t)img * 4107 + (size_t)p * 37 + q;
#pragma unroll
    for (int oc = 0; oc < 3; oc++) {
        float m = acc[oc][0][0];
#pragma unroll
        for (int pr = 0; pr < 3; pr++)
#pragma unroll
            for (int pc = 0; pc < 3; pc++) m = fmaxf(m, acc[oc][pr][pc]);
        g_pool1[ob + oc * 1369] = fmaxf(m + bsh[oc], 0.f);
    }
}

// ---------------------------------------------------------------------------
// Stage 2: conv2 + maxpool3 + relu + 36->6 linear. One block per image.
// Block 0 additionally streams stage3's big weights to warm L2.
// ---------------------------------------------------------------------------
__global__ __launch_bounds__(128) void stage2_kernel(
    const float* __restrict__ w2g,   // [1][3][3][3]
    const float* __restrict__ b2g,   // [1]
    const float* __restrict__ linw,  // [6][36]
    const float* __restrict__ linb,  // [6]
    const float* __restrict__ fc1w,  // warmed for stage3
    const float* __restrict__ fc2w)
{
    const int img = blockIdx.x;
    const int tid = threadIdx.x;

    __shared__ float s[3 * 1369];
    __shared__ float s2[36];

    const float* src = g_pool1 + (size_t)img * 4107;
    for (int i = tid; i < 4107; i += blockDim.x) s[i] = src[i];

    float w[27];
#pragma unroll
    for (int i = 0; i < 27; i++) w[i] = w2g[i];
    const float bias = b2g[0];

    // L2 warm-up of stage3 weights (block 0 only)
    if (img == 0) {
        float acc = 0.f;
        const float4* p1 = (const float4*)fc1w;
        for (int i = tid; i < 7200; i += 128) {
            float4 v = p1[i]; acc += v.x + v.y + v.z + v.w;
        }
        const float4* p2 = (const float4*)fc2w;
        for (int i = tid; i < 1800; i += 128) {
            float4 v = p2[i]; acc += v.x + v.y + v.z + v.w;
        }
        if (acc == -1.2345678e33f) g_sink = acc;   // never true; keeps loads live
    }
    __syncthreads();

    if (tid < 36) {
        const int pr = tid / 6, pc = tid - 6 * pr;
        float pool = -1e30f;
#pragma unroll
        for (int r = 0; r < 3; r++) {
#pragma unroll
            for (int c = 0; c < 3; c++) {
                const int R = 3 * pr + r;
                const int C = 3 * pc + c;
                float a = bias;
#pragma unroll
                for (int ci = 0; ci < 3; ci++)
#pragma unroll
                    for (int kh = 0; kh < 3; kh++)
#pragma unroll
                        for (int kw = 0; kw < 3; kw++)
                            a = fmaf(s[ci * 1369 + (2 * R + kh) * 37 + 2 * C + kw],
                                     w[ci * 9 + kh * 3 + kw], a);
                pool = fmaxf(pool, a);
            }
        }
        s2[tid] = fmaxf(pool, 0.f);
    }
    __syncthreads();

    if (tid < 6) {
        float a = linb[tid];
#pragma unroll
        for (int k = 0; k < 36; k++) a = fmaf(s2[k], linw[tid * 36 + k], a);
        g_nf[img * 6 + tid] = a;
    }
}

// ---------------------------------------------------------------------------
// Stage 3: message passing + MLP head. One block per node, 256 threads.
// Split-K across thread pairs (tid, tid+128) with float4 loads.
// ---------------------------------------------------------------------------
__global__ __launch_bounds__(256) void stage3_kernel(
    const float* __restrict__ pos,     // [64,5,4,6]
    const float* __restrict__ attmap,  // [64,5,4,4]
    const float* __restrict__ framew, const float* __restrict__ frameb,
    const float* __restrict__ lastw,  const float* __restrict__ lastb,
    const float* __restrict__ fc1w,   const float* __restrict__ fc1b,
    const float* __restrict__ fc2w,   const float* __restrict__ fc2b,
    const float* __restrict__ fc3w,   const float* __restrict__ fc3b,
    float* __restrict__ out)
{
    const int n   = blockIdx.x;
    const int tid = threadIdx.x;
    const int half = tid >> 7;        // 0 or 1
    const int o    = tid & 127;

    __shared__ float msg[120];
    __shared__ __align__(16) float feat[240];
    __shared__ __align__(16) float h1[120];
    __shared__ __align__(16) float h2[60];
    __shared__ float part1[240];
    __shared__ float part2[120];
    __shared__ float part3[12];

    const float* posn = pos + n * 120;

    if (tid < 120) {
        const int f = tid / 24;
        const int j = (tid / 6) % 4;
        const int d = tid % 6;
        float acc = frameb[d];
#pragma unroll
        for (int e = 0; e < 6; e++)
            acc = fmaf(posn[(f * 4 + j) * 6 + e], framew[d * 6 + e], acc);
        msg[tid] = acc;
        feat[f * 48 + j * 12 + d] = g_nf[(n * 20 + f * 4 + j) * 6 + d];
    }
    __syncthreads();

    if (tid < 120) {
        const int f  = tid / 24;
        const int nn = (tid / 6) % 4;
        const int d  = tid % 6;
        const float* att = attmap + n * 80 + f * 16;
        float acc = 0.f;
#pragma unroll
        for (int j = 0; j < 4; j++)
            acc = fmaf(att[j * 4 + nn], msg[f * 24 + j * 6 + d], acc);
        if (f >= 1) {
            float l = lastb[d];
#pragma unroll
            for (int e = 0; e < 6; e++)
                l = fmaf(posn[((f - 1) * 4 + nn) * 6 + e], lastw[d * 6 + e], l);
            acc += l;
        }
        feat[f * 48 + nn * 12 + 6 + d] = acc;
    }
    __syncthreads();

    // fc1: 120 outputs, K=240 split into two 120-halves (30 float4 each)
    if (o < 120) {
        const float4* wr = (const float4*)(fc1w + o * 240 + half * 120);
        const float4* fe = (const float4*)feat + half * 30;
        float acc = 0.f;
#pragma unroll
        for (int k = 0; k < 30; k++) {
            float4 w4 = wr[k], f4 = fe[k];
            acc = fmaf(f4.x, w4.x, acc);
            acc = fmaf(f4.y, w4.y, acc);
            acc = fmaf(f4.z, w4.z, acc);
            acc = fmaf(f4.w, w4.w, acc);
        }
        part1[half * 120 + o] = acc;
    }
    __syncthreads();
    if (tid < 120) h1[tid] = fmaxf(part1[tid] + part1[120 + tid] + fc1b[tid], 0.f);
    __syncthreads();

    // fc2: 60 outputs, K=120 split into two 60-halves (15 float4 each)
    if (o < 60) {
        const float4* wr = (const float4*)(fc2w + o * 120 + half * 60);
        const float4* hh = (const float4*)h1 + half * 15;
        float acc = 0.f;
#pragma unroll
        for (int k = 0; k < 15; k++) {
            float4 w4 = wr[k], f4 = hh[k];
            acc = fmaf(f4.x, w4.x, acc);
            acc = fmaf(f4.y, w4.y, acc);
            acc = fmaf(f4.z, w4.z, acc);
            acc = fmaf(f4.w, w4.w, acc);
        }
        part2[half * 60 + o] = acc;
    }
    __syncthreads();
    if (tid < 60) h2[tid] = fmaxf(part2[tid] + part2[60 + tid] + fc2b[tid], 0.f);
    __syncthreads();

    // fc3: 6 outputs, K=60 split into two 30-halves (15 float2 each)
    if (o < 6) {
        const float2* wr = (const float2*)(fc3w + o * 60 + half * 30);
        const float2* hh = (const float2*)h2 + half * 15;
        float acc = 0.f;
#pragma unroll
        for (int k = 0; k < 15; k++) {
            float2 w2 = wr[k], f2 = hh[k];
            acc = fmaf(f2.x, w2.x, acc);
            acc = fmaf(f2.y, w2.y, acc);
        }
        part3[half * 6 + o] = acc;
    }
    __syncthreads();
    if (tid < 6) out[n * 6 + tid] = part3[tid] + part3[6 + tid] + fc3b[tid];
}

// ---------------------------------------------------------------------------
extern "C" void kernel_launch(void* const* d_in, const int* in_sizes, int n_in,
                              void* d_out, int out_size)
{
    const float* nodes  = (const float*)d_in[0];
    const float* pos    = (const float*)d_in[1];
    const float* attmap = (const float*)d_in[2];
    // d_in[3] = depths (unused)
    const float* conv1w = (const float*)d_in[4];
    const float* conv1b = (const float*)d_in[5];
    const float* conv2w = (const float*)d_in[6];
    const float* conv2b = (const float*)d_in[7];
    const float* linw   = (const float*)d_in[8];
    const float* linb   = (const float*)d_in[9];
    const float* framew = (const float*)d_in[10];
    const float* frameb = (const float*)d_in[11];
    const float* lastw  = (const float*)d_in[12];
    const float* lastb  = (const float*)d_in[13];
    const float* fc1w   = (const float*)d_in[14];
    const float* fc1b   = (const float*)d_in[15];
    const float* fc2w   = (const float*)d_in[16];
    const float* fc2b   = (const float*)d_in[17];
    const float* fc3w   = (const float*)d_in[18];
    const float* fc3b   = (const float*)d_in[19];

    dim3 g1(IMGS, 11);
    stage1_kernel<<<g1, 128>>>(nodes, conv1w, conv1b);
    stage2_kernel<<<IMGS, 128>>>(conv2w, conv2b, linw, linb, fc1w, fc2w);
    stage3_kernel<<<64, 256>>>(pos, attmap, framew, frameb, lastw, lastb,
                               fc1w, fc1b, fc2w, fc2b, fc3w, fc3b,
                               (float*)d_out);
}

// round 8
// speedup vs baseline: 1.6573x; 1.0121x over previous
#include <cuda_runtime.h>
#include <cstddef>

#define IMGS 1280

__device__ float g_pool1[IMGS * 3 * 37 * 37];   // 21 MB scratch
__device__ float g_nf[IMGS * 6];
__device__ float g_sink;                        // DCE-blocker for L2 warmup

// ---------------------------------------------------------------------------
// Stage 1: conv1(3->3,k3,s2) + maxpool3 + relu, streamed directly from GMEM.
// Grid (1280, 11) x 128 threads; thread = one pooled cell (p,q).
// Per input channel: batch-load the full 7x8 window (28 independent LDG.64)
// into registers FIRST, then FMA -> MLP_eff ~28 instead of ~4, hiding DRAM
// latency without smem staging.
// ---------------------------------------------------------------------------
__global__ __launch_bounds__(128) void stage1_kernel(
    const float* __restrict__ nodes,
    const float* __restrict__ w1g,     // [oc][ci][3][3]
    const float* __restrict__ b1g)     // [3]
{
    __shared__ float w1s[81];          // [ci][oc][kh][kw]
    __shared__ float bsh[3];

    const int tid = threadIdx.x;
    if (tid < 81) {
        int oc = tid / 27, rem = tid - oc * 27;
        int ci = rem / 9,  k   = rem - ci * 9;
        w1s[ci * 27 + oc * 9 + k] = w1g[tid];
    }
    if (tid < 3) bsh[tid] = b1g[tid];
    __syncthreads();

    const int img  = blockIdx.x;
    const int cell = blockIdx.y * 128 + tid;     // 0..1407 (1369 valid)
    if (cell >= 1369) return;
    const int p = cell / 37;
    const int q = cell - p * 37;

    const float* base0 = nodes + (size_t)img * 150528 + (size_t)(6 * p) * 224 + 6 * q;

    float acc[3][3][3];   // [oc][pr][pc]
#pragma unroll
    for (int oc = 0; oc < 3; oc++)
#pragma unroll
        for (int pr = 0; pr < 3; pr++)
#pragma unroll
            for (int pc = 0; pc < 3; pc++) acc[oc][pr][pc] = 0.f;

#pragma unroll
    for (int ci = 0; ci < 3; ci++) {
        // ---- batch-load the whole 7-row window for this channel ----
        float2 rb[7][4];
        const float* base = base0 + ci * 50176;
#pragma unroll
        for (int r = 0; r < 7; r++) {
            const float2* rp = (const float2*)(base + r * 224);
#pragma unroll
            for (int j = 0; j < 4; j++) rb[r][j] = __ldg(rp + j);
        }

        float wl[27];
#pragma unroll
        for (int j = 0; j < 27; j++) wl[j] = w1s[ci * 27 + j];

        // ---- consume ----
#pragma unroll
        for (int r = 0; r < 7; r++) {
            float v[7] = {rb[r][0].x, rb[r][0].y, rb[r][1].x, rb[r][1].y,
                          rb[r][2].x, rb[r][2].y, rb[r][3].x};
#pragma unroll
            for (int pr = 0; pr < 3; pr++) {
                const int kh = r - 2 * pr;
                if (kh >= 0 && kh < 3) {
#pragma unroll
                    for (int oc = 0; oc < 3; oc++)
#pragma unroll
                        for (int pc = 0; pc < 3; pc++)
#pragma unroll
                            for (int kw = 0; kw < 3; kw++)
                                acc[oc][pr][pc] =
                                    fmaf(v[2 * pc + kw],
                                         wl[oc * 9 + kh * 3 + kw],
                                         acc[oc][pr][pc]);
                }
            }
        }
    }

    const size_t ob = (size_t)img * 4107 + (size_t)p * 37 + q;
#pragma unroll
    for (int oc = 0; oc < 3; oc++) {
        float m = acc[oc][0][0];
#pragma unroll
        for (int pr = 0; pr < 3; pr++)
#pragma unroll
            for (int pc = 0; pc < 3; pc++) m = fmaxf(m, acc[oc][pr][pc]);
        g_pool1[ob + oc * 1369] = fmaxf(m + bsh[oc], 0.f);
    }
}

// ---------------------------------------------------------------------------
// Stage 2: conv2 + maxpool3 + relu + 36->6 linear. One block per image.
// Block 0 additionally streams stage3's big weights to warm L2.
// ---------------------------------------------------------------------------
__global__ __launch_bounds__(128) void stage2_kernel(
    const float* __restrict__ w2g,   // [1][3][3][3]
    const float* __restrict__ b2g,   // [1]
    const float* __restrict__ linw,  // [6][36]
    const float* __restrict__ linb,  // [6]
    const float* __restrict__ fc1w,  // warmed for stage3
    const float* __restrict__ fc2w)
{
    const int img = blockIdx.x;
    const int tid = threadIdx.x;

    __shared__ float s[3 * 1369];
    __shared__ float s2[36];

    const float* src = g_pool1 + (size_t)img * 4107;
    for (int i = tid; i < 4107; i += blockDim.x) s[i] = src[i];

    float w[27];
#pragma unroll
    for (int i = 0; i < 27; i++) w[i] = w2g[i];
    const float bias = b2g[0];

    // L2 warm-up of stage3 weights (block 0 only)
    if (img == 0) {
        float acc = 0.f;
        const float4* p1 = (const float4*)fc1w;
        for (int i = tid; i < 7200; i += 128) {
            float4 v = p1[i]; acc += v.x + v.y + v.z + v.w;
        }
        const float4* p2 = (const float4*)fc2w;
        for (int i = tid; i < 1800; i += 128) {
            float4 v = p2[i]; acc += v.x + v.y + v.z + v.w;
        }
        if (acc == -1.2345678e33f) g_sink = acc;   // never true; keeps loads live
    }
    __syncthreads();

    if (tid < 36) {
        const int pr = tid / 6, pc = tid - 6 * pr;
        float pool = -1e30f;
#pragma unroll
        for (int r = 0; r < 3; r++) {
#pragma unroll
            for (int c = 0; c < 3; c++) {
                const int R = 3 * pr + r;
                const int C = 3 * pc + c;
                float a = bias;
#pragma unroll
                for (int ci = 0; ci < 3; ci++)
#pragma unroll
                    for (int kh = 0; kh < 3; kh++)
#pragma unroll
                        for (int kw = 0; kw < 3; kw++)
                            a = fmaf(s[ci * 1369 + (2 * R + kh) * 37 + 2 * C + kw],
                                     w[ci * 9 + kh * 3 + kw], a);
                pool = fmaxf(pool, a);
            }
        }
        s2[tid] = fmaxf(pool, 0.f);
    }
    __syncthreads();

    if (tid < 6) {
        float a = linb[tid];
#pragma unroll
        for (int k = 0; k < 36; k++) a = fmaf(s2[k], linw[tid * 36 + k], a);
        g_nf[img * 6 + tid] = a;
    }
}

// ---------------------------------------------------------------------------
// Stage 3: message passing + MLP head. One block per node, 256 threads.
// Split-K across thread pairs (tid, tid+128) with float4 loads.
// ---------------------------------------------------------------------------
__global__ __launch_bounds__(256) void stage3_kernel(
    const float* __restrict__ pos,     // [64,5,4,6]
    const float* __restrict__ attmap,  // [64,5,4,4]
    const float* __restrict__ framew, const float* __restrict__ frameb,
    const float* __restrict__ lastw,  const float* __restrict__ lastb,
    const float* __restrict__ fc1w,   const float* __restrict__ fc1b,
    const float* __restrict__ fc2w,   const float* __restrict__ fc2b,
    const float* __restrict__ fc3w,   const float* __restrict__ fc3b,
    float* __restrict__ out)
{
    const int n   = blockIdx.x;
    const int tid = threadIdx.x;
    const int half = tid >> 7;        // 0 or 1
    const int o    = tid & 127;

    __shared__ float msg[120];
    __shared__ __align__(16) float feat[240];
    __shared__ __align__(16) float h1[120];
    __shared__ __align__(16) float h2[60];
    __shared__ float part1[240];
    __shared__ float part2[120];
    __shared__ float part3[12];

    const float* posn = pos + n * 120;

    if (tid < 120) {
        const int f = tid / 24;
        const int j = (tid / 6) % 4;
        const int d = tid % 6;
        float acc = frameb[d];
#pragma unroll
        for (int e = 0; e < 6; e++)
            acc = fmaf(posn[(f * 4 + j) * 6 + e], framew[d * 6 + e], acc);
        msg[tid] = acc;
        feat[f * 48 + j * 12 + d] = g_nf[(n * 20 + f * 4 + j) * 6 + d];
    }
    __syncthreads();

    if (tid < 120) {
        const int f  = tid / 24;
        const int nn = (tid / 6) % 4;
        const int d  = tid % 6;
        const float* att = attmap + n * 80 + f * 16;
        float acc = 0.f;
#pragma unroll
        for (int j = 0; j < 4; j++)
            acc = fmaf(att[j * 4 + nn], msg[f * 24 + j * 6 + d], acc);
        if (f >= 1) {
            float l = lastb[d];
#pragma unroll
            for (int e = 0; e < 6; e++)
                l = fmaf(posn[((f - 1) * 4 + nn) * 6 + e], lastw[d * 6 + e], l);
            acc += l;
        }
        feat[f * 48 + nn * 12 + 6 + d] = acc;
    }
    __syncthreads();

    // fc1: 120 outputs, K=240 split into two 120-halves (30 float4 each)
    if (o < 120) {
        const float4* wr = (const float4*)(fc1w + o * 240 + half * 120);
        const float4* fe = (const float4*)feat + half * 30;
        float acc = 0.f;
#pragma unroll
        for (int k = 0; k < 30; k++) {
            float4 w4 = wr[k], f4 = fe[k];
            acc = fmaf(f4.x, w4.x, acc);
            acc = fmaf(f4.y, w4.y, acc);
            acc = fmaf(f4.z, w4.z, acc);
            acc = fmaf(f4.w, w4.w, acc);
        }
        part1[half * 120 + o] = acc;
    }
    __syncthreads();
    if (tid < 120) h1[tid] = fmaxf(part1[tid] + part1[120 + tid] + fc1b[tid], 0.f);
    __syncthreads();

    // fc2: 60 outputs, K=120 split into two 60-halves (15 float4 each)
    if (o < 60) {
        const float4* wr = (const float4*)(fc2w + o * 120 + half * 60);
        const float4* hh = (const float4*)h1 + half * 15;
        float acc = 0.f;
#pragma unroll
        for (int k = 0; k < 15; k++) {
            float4 w4 = wr[k], f4 = hh[k];
            acc = fmaf(f4.x, w4.x, acc);
            acc = fmaf(f4.y, w4.y, acc);
            acc = fmaf(f4.z, w4.z, acc);
            acc = fmaf(f4.w, w4.w, acc);
        }
        part2[half * 60 + o] = acc;
    }
    __syncthreads();
    if (tid < 60) h2[tid] = fmaxf(part2[tid] + part2[60 + tid] + fc2b[tid], 0.f);
    __syncthreads();

    // fc3: 6 outputs, K=60 split into two 30-halves (15 float2 each)
    if (o < 6) {
        const float2* wr = (const float2*)(fc3w + o * 60 + half * 30);
        const float2* hh = (const float2*)h2 + half * 15;
        float acc = 0.f;
#pragma unroll
        for (int k = 0; k < 15; k++) {
            float2 w2 = wr[k], f2 = hh[k];
            acc = fmaf(f2.x, w2.x, acc);
            acc = fmaf(f2.y, w2.y, acc);
        }
        part3[half * 6 + o] = acc;
    }
    __syncthreads();
    if (tid < 6) out[n * 6 + tid] = part3[tid] + part3[6 + tid] + fc3b[tid];
}

// ---------------------------------------------------------------------------
extern "C" void kernel_launch(void* const* d_in, const int* in_sizes, int n_in,
                              void* d_out, int out_size)
{
    const float* nodes  = (const float*)d_in[0];
    const float* pos    = (const float*)d_in[1];
    const float* attmap = (const float*)d_in[2];
    // d_in[3] = depths (unused)
    const float* conv1w = (const float*)d_in[4];
    const float* conv1b = (const float*)d_in[5];
    const float* conv2w = (const float*)d_in[6];
    const float* conv2b = (const float*)d_in[7];
    const float* linw   = (const float*)d_in[8];
    const float* linb   = (const float*)d_in[9];
    const float* framew = (const float*)d_in[10];
    const float* frameb = (const float*)d_in[11];
    const float* lastw  = (const float*)d_in[12];
    const float* lastb  = (const float*)d_in[13];
    const float* fc1w   = (const float*)d_in[14];
    const float* fc1b   = (const float*)d_in[15];
    const float* fc2w   = (const float*)d_in[16];
    const float* fc2b   = (const float*)d_in[17];
    const float* fc3w   = (const float*)d_in[18];
    const float* fc3b   = (const float*)d_in[19];

    dim3 g1(IMGS, 11);
    stage1_kernel<<<g1, 128>>>(nodes, conv1w, conv1b);
    stage2_kernel<<<IMGS, 128>>>(conv2w, conv2b, linw, linb, fc1w, fc2w);
    stage3_kernel<<<64, 256>>>(pos, attmap, framew, frameb, lastw, lastb,
                               fc1w, fc1b, fc2w, fc2b, fc3w, fc3b,
                               (float*)d_out);
}